// round 3
// baseline (speedup 1.0000x reference)
#include <cuda_runtime.h>
#include <cstdint>

// Problem constants (fixed by the dataset)
#define NWIN   65536      // B * NW = 2048 * 32 query windows
#define DIM    128        // window / codebook dim
#define KCB    2048       // codebook entries
#define MT     128        // windows per block
#define KT     128        // codebook entries per k-tile
#define NKT    (KCB / KT) // 16 k-tiles

// Precomputed ||c_k||^2
__device__ float g_cnorm[KCB];

// ---------------------------------------------------------------------------
// Kernel 1: codebook squared norms. One warp per codebook row.
// ---------------------------------------------------------------------------
__global__ void cnorm_kernel(const float* __restrict__ cb) {
    int warp = (blockIdx.x * blockDim.x + threadIdx.x) >> 5;
    int lane = threadIdx.x & 31;
    if (warp >= KCB) return;
    const float4* row = (const float4*)(cb + (size_t)warp * DIM);
    float4 v = row[lane];                       // 32 lanes x float4 = 128 floats
    float s = v.x * v.x + v.y * v.y + v.z * v.z + v.w * v.w;
    #pragma unroll
    for (int o = 16; o; o >>= 1) s += __shfl_xor_sync(0xFFFFFFFFu, s, o);
    if (lane == 0) g_cnorm[warp] = s;
}

// packed f32x2 FMA: acc = a * b + acc (elementwise on the two packed floats)
__device__ __forceinline__ void fma_f32x2(unsigned long long& acc,
                                          unsigned long long a,
                                          unsigned long long b) {
    asm("fma.rn.f32x2 %0, %1, %2, %0;" : "+l"(acc) : "l"(a), "l"(b));
}

__device__ __forceinline__ float pair_sum(unsigned long long p) {
    float lo = __uint_as_float((unsigned)(p & 0xFFFFFFFFull));
    float hi = __uint_as_float((unsigned)(p >> 32));
    return lo + hi;
}

// ---------------------------------------------------------------------------
// Kernel 2: fused score-GEMM + argmin + gather.
//   Block: 128 windows x all 2048 codebook entries (16 k-tiles of 128).
//   256 threads as (tx in [0,16), ty in [0,16)); each thread: 8 m-rows x 8 k-cols.
//   smem tiles stored d2-major as packed float2 (ull) so inner-loop frag loads
//   are LDS.128. b-frag k-columns strided: k(j) = 32*(j/2) + 2*tx + (j&1) so a
//   warp's simultaneous LDS.128s cover a contiguous 256B span (conflict-free).
// ---------------------------------------------------------------------------
__global__ __launch_bounds__(256, 1)
void vq_kernel(const float* __restrict__ ze,
               const float* __restrict__ cb,
               float* __restrict__ out) {
    extern __shared__ unsigned long long smem[];
    unsigned long long* zs = smem;             // [64][128] packed f32x2: (d2, m)
    unsigned long long* cs = smem + 64 * 128;  // [64][128] packed f32x2: (d2, k)

    const int tid = threadIdx.x;
    const int tx  = tid & 15;
    const int ty  = tid >> 4;
    const int m0  = blockIdx.x * MT;

    // --- load z tile (fully contiguous 128*128 floats) transposed into zs ---
    {
        const unsigned long long* zg = (const unsigned long long*)(ze + (size_t)m0 * DIM);
        #pragma unroll
        for (int i = tid; i < MT * 64; i += 256) {
            int m = i >> 6, d2 = i & 63;
            zs[d2 * 128 + m] = zg[i];
        }
    }

    float minv[8];
    int   mini[8];
    #pragma unroll
    for (int i = 0; i < 8; i++) { minv[i] = 3.4e38f; mini[i] = 0; }

    for (int kt = 0; kt < NKT; kt++) {
        __syncthreads();
        const unsigned long long* cg =
            (const unsigned long long*)(cb + (size_t)kt * KT * DIM);
        #pragma unroll
        for (int i = tid; i < KT * 64; i += 256) {
            int k = i >> 6, d2 = i & 63;
            cs[d2 * 128 + k] = cg[i];
        }
        __syncthreads();

        unsigned long long acc[8][8];
        #pragma unroll
        for (int i = 0; i < 8; i++)
            #pragma unroll
            for (int j = 0; j < 8; j++) acc[i][j] = 0ull;

        #pragma unroll 2
        for (int d2 = 0; d2 < 64; d2++) {
            unsigned long long a[8], b[8];
            const ulonglong2* za = (const ulonglong2*)(zs + d2 * 128 + ty * 8);
            const ulonglong2* cbase = (const ulonglong2*)(cs + d2 * 128);
            #pragma unroll
            for (int c = 0; c < 4; c++) {
                ulonglong2 av = za[c];
                a[2 * c] = av.x; a[2 * c + 1] = av.y;
                ulonglong2 bv = cbase[tx + 16 * c];
                b[2 * c] = bv.x; b[2 * c + 1] = bv.y;
            }
            #pragma unroll
            for (int i = 0; i < 8; i++)
                #pragma unroll
                for (int j = 0; j < 8; j++)
                    fma_f32x2(acc[i][j], a[i], b[j]);
        }

        // epilogue for this k-tile: score = ||c||^2 - 2*dot, running argmin
        #pragma unroll
        for (int j = 0; j < 8; j++) {
            int k = kt * KT + 32 * (j >> 1) + 2 * tx + (j & 1);
            float cn = g_cnorm[k];
            #pragma unroll
            for (int i = 0; i < 8; i++) {
                float s = fmaf(-2.0f, pair_sum(acc[i][j]), cn);
                if (s < minv[i]) { minv[i] = s; mini[i] = k; }
            }
        }
    }

    // --- cross-thread argmin reduction (16 tx partials per m-row) ---
    __syncthreads();
    float* rv = (float*)cs;                 // [16][132] (padded stride)
    int*   ri = (int*)(rv + 16 * 132);      // [16][132]
    #pragma unroll
    for (int i = 0; i < 8; i++) {
        int m = ty * 8 + i;
        rv[tx * 132 + m] = minv[i];
        ri[tx * 132 + m] = mini[i];
    }
    __syncthreads();
    int* fidx = (int*)zs;                   // final index per m-row
    if (tid < MT) {
        int m = tid;
        float bv = rv[m];
        int   bi = ri[m];
        #pragma unroll
        for (int t = 1; t < 16; t++) {
            float v = rv[t * 132 + m];
            int  id = ri[t * 132 + m];
            if (v < bv || (v == bv && id < bi)) { bv = v; bi = id; }
        }
        fidx[m] = bi;
    }
    __syncthreads();

    // --- gather + write output (codebook is L2-hot, 1 MB total) ---
    const float4* cb4 = (const float4*)cb;
    float4* out4 = (float4*)out;
    #pragma unroll
    for (int i = tid; i < MT * (DIM / 4); i += 256) {
        int m = i >> 5;                     // DIM/4 = 32 float4 per row
        int c = i & 31;
        int idx = fidx[m];
        out4[(size_t)(m0 + m) * 32 + c] = cb4[(size_t)idx * 32 + c];
    }
}

// ---------------------------------------------------------------------------
extern "C" void kernel_launch(void* const* d_in, const int* in_sizes, int n_in,
                              void* d_out, int out_size) {
    const float* ze = (const float*)d_in[0];   // [2048, 4096] == [65536, 128]
    const float* cb = (const float*)d_in[1];   // [2048, 128]
    float* out = (float*)d_out;                // [65536, 128]

    (void)in_sizes; (void)n_in; (void)out_size;

    cudaFuncSetAttribute(vq_kernel,
                         cudaFuncAttributeMaxDynamicSharedMemorySize,
                         131072);

    cnorm_kernel<<<KCB / 8, 256>>>(cb);
    vq_kernel<<<NWIN / MT, 256, 131072>>>(ze, cb, out);
}

// round 5
// speedup vs baseline: 1.8587x; 1.8587x over previous
#include <cuda_runtime.h>
#include <cstdint>

// ---------------------------------------------------------------------------
// Problem constants
// ---------------------------------------------------------------------------
#define NWIN   65536
#define DIM    128
#define KCB    2048
#define MT     128              // windows per CTA
#define NTILE  16               // n-tiles of 128 codes
#define NSTG   64               // pipeline stages: (tile, k32-stage) pairs
#define STG_FLOATS 8192         // one stage = 32 KB = k32 x (bh+bl) frag image

// smem layout (float offsets)
#define ZH_OFF   0              // zh frag image: 16 sg x 8 mf x 32 lane x 4
#define ZL_OFF   16384
#define BB_OFF   32768          // B double buffer: 2 x 8192
#define CN_OFF   49152          // 2048 codebook norms
#define SMEM_FLOATS 51200
#define SMEM_BYTES  (SMEM_FLOATS * 4)

__device__ float g_cnorm[KCB];
__device__ float g_Bimg[NSTG * STG_FLOATS];   // 2 MB fragment-major tf32 image

// ---------------------------------------------------------------------------
// Helpers
// ---------------------------------------------------------------------------
__device__ __forceinline__ uint32_t to_tf32(float x) {
    uint32_t r;
    asm("cvt.rna.tf32.f32 %0, %1;" : "=r"(r) : "f"(x));
    return r;
}
__device__ __forceinline__ uint32_t smem_u32(const void* p) {
    uint32_t a;
    asm("{ .reg .u64 t; cvta.to.shared.u64 t, %1; cvt.u32.u64 %0, t; }"
        : "=r"(a) : "l"(p));
    return a;
}

// m16n8k8 tf32 MMA, D += A*B (fp32 accum)
#define MMA(d, a, b) \
    asm volatile("mma.sync.aligned.m16n8k8.row.col.f32.tf32.tf32.f32 " \
        "{%0,%1,%2,%3},{%4,%5,%6,%7},{%8,%9},{%0,%1,%2,%3};" \
        : "+f"((d)[0]), "+f"((d)[1]), "+f"((d)[2]), "+f"((d)[3]) \
        : "r"((a)[0]), "r"((a)[1]), "r"((a)[2]), "r"((a)[3]), \
          "r"((b)[0]), "r"((b)[1]))

#define CP16(dst, src) \
    asm volatile("cp.async.cg.shared.global [%0], [%1], 16;" \
                 :: "r"(dst), "l"(src) : "memory")
#define CP_COMMIT() asm volatile("cp.async.commit_group;" ::: "memory")

// ---------------------------------------------------------------------------
// Prep 1: codebook squared norms (exact fp32)
// ---------------------------------------------------------------------------
__global__ void cnorm_kernel(const float* __restrict__ cb) {
    int warp = (blockIdx.x * blockDim.x + threadIdx.x) >> 5;
    int lane = threadIdx.x & 31;
    if (warp >= KCB) return;
    const float4* row = (const float4*)(cb + (size_t)warp * DIM);
    float4 v = row[lane];
    float s = v.x * v.x + v.y * v.y + v.z * v.z + v.w * v.w;
    #pragma unroll
    for (int o = 16; o; o >>= 1) s += __shfl_xor_sync(0xFFFFFFFFu, s, o);
    if (lane == 0) g_cnorm[warp] = s;
}

// ---------------------------------------------------------------------------
// Prep 2: build fragment-major tf32 B image.
// Stage stg = (tile t, k32-stage st). Element layout within a stage:
//   i = ((s*2 + hl)*16 + f)*64 + lane*2 + reg
//   code n = t*128 + f*8 + (lane>>2)
//   k      = st*32 + s*8 + (lane&3) + 4*reg
//   hl==0 -> ch = tf32(c), hl==1 -> cl = tf32(c - ch)
// This matches the mma.sync B-fragment (b0: k=l&3, b1: k=(l&3)+4, n=l>>2),
// so the main kernel loads each B fragment pair with one LDS.64.
// ---------------------------------------------------------------------------
__global__ __launch_bounds__(256) void bprep_kernel(const float* __restrict__ cb) {
    int stg = blockIdx.x;
    int t = stg >> 2, st = stg & 3;
    for (int i = threadIdx.x; i < STG_FLOATS; i += 256) {
        int reg  = i & 1;
        int lane = (i >> 1) & 31;
        int f    = (i >> 6) & 15;
        int hl   = (i >> 10) & 1;
        int s    = (i >> 11) & 3;
        int n = t * 128 + f * 8 + (lane >> 2);
        int k = st * 32 + s * 8 + (lane & 3) + 4 * reg;
        float v = cb[(size_t)n * DIM + k];
        uint32_t hb = to_tf32(v);
        uint32_t out = hb;
        if (hl) out = to_tf32(v - __uint_as_float(hb));
        g_Bimg[(size_t)stg * STG_FLOATS + i] = __uint_as_float(out);
    }
}

// ---------------------------------------------------------------------------
// Main kernel: 512 CTAs x 256 threads, 1 CTA/SM.
//   8 warps = 2(m) x 4(n); warp tile 64 rows x 32 codes; acc 4x4 m16n8 tiles.
//   zh/zl pre-fragged in smem (LDS.128 per A frag), B streamed via cp.async
//   double buffer from the pre-fragged global image (LDS.64 per B frag).
//   Each thread owns 8 fixed rows -> register-resident running argmin.
// ---------------------------------------------------------------------------
__global__ __launch_bounds__(256, 1)
void vq_main(const float* __restrict__ ze,
             const float* __restrict__ cb,
             float* __restrict__ out) {
    extern __shared__ float sm[];
    const uint32_t sb = smem_u32(sm);
    const int tid  = threadIdx.x;
    const int wid  = tid >> 5;
    const int lane = tid & 31;
    const int wm   = wid & 1;       // m half (rows wm*64 .. +63)
    const int wn   = wid >> 1;      // n quarter (codes wn*32 .. +31 per tile)
    const int m0   = blockIdx.x * MT;

    // ---- prime the B pipeline: stage 0 -> buffer 0 (8 x 16B per thread) ----
    {
        const float* src = g_Bimg + tid * 4;
        uint32_t dst = sb + (BB_OFF + tid * 4) * 4;
        #pragma unroll
        for (int j = 0; j < 8; j++)
            CP16(dst + j * 4096, src + j * 1024);
        CP_COMMIT();
    }

    // ---- codebook norms -> smem ----
    for (int i = tid; i < KCB; i += 256) sm[CN_OFF + i] = g_cnorm[i];

    // ---- build zh / zl fragment images (overlaps the stage-0 copy) ----
    // image idx: ((sg*8 + mf)*32 + l)*4 + reg,
    //   row m = mf*16 + (l>>2) + 8*(reg&1), col k = sg*8 + (l&3) + 4*(reg>>1)
    for (int i = tid; i < MT * DIM; i += 256) {
        int m = i >> 7, k = i & 127;
        float v = ze[(size_t)(m0 + m) * DIM + k];
        uint32_t hb = to_tf32(v);
        uint32_t lb = to_tf32(v - __uint_as_float(hb));
        int sg = k >> 3, mf = m >> 4, r = m & 15;
        int l   = ((r & 7) << 2) | (k & 3);
        int reg = (((k >> 2) & 1) << 1) | (r >> 3);
        int idx = ((sg * 8 + mf) * 32 + l) * 4 + reg;
        sm[ZH_OFF + idx] = __uint_as_float(hb);
        sm[ZL_OFF + idx] = __uint_as_float(lb);
    }

    float acc[4][4][4];
    #pragma unroll
    for (int a = 0; a < 4; a++)
        #pragma unroll
        for (int b = 0; b < 4; b++)
            #pragma unroll
            for (int c = 0; c < 4; c++) acc[a][b][c] = 0.0f;

    float minv[8];
    int   mini[8];
    #pragma unroll
    for (int i = 0; i < 8; i++) { minv[i] = 3.4e38f; mini[i] = 0; }

    const uint4* ZH = (const uint4*)(sm + ZH_OFF);
    const uint4* ZL = (const uint4*)(sm + ZL_OFF);

    // ---- main pipeline over 64 stages ----
    for (int st = 0; st < NSTG; st++) {
        // issue next stage copy into the other buffer
        if (st < NSTG - 1) {
            const float* src = g_Bimg + (size_t)(st + 1) * STG_FLOATS + tid * 4;
            uint32_t dst = sb + (BB_OFF + ((st + 1) & 1) * STG_FLOATS + tid * 4) * 4;
            #pragma unroll
            for (int j = 0; j < 8; j++)
                CP16(dst + j * 4096, src + j * 1024);
            CP_COMMIT();
            asm volatile("cp.async.wait_group 1;" ::: "memory");
        } else {
            asm volatile("cp.async.wait_group 0;" ::: "memory");
        }
        __syncthreads();

        const uint2* Bp = (const uint2*)(sm + BB_OFF + (st & 1) * STG_FLOATS);
        const int sti = st & 3;                 // k32-stage within tile

        #pragma unroll
        for (int s = 0; s < 4; s++) {
            const int sg = sti * 4 + s;         // k8 index 0..15
            uint32_t ah[4][4], al[4][4], bh[4][2], bl[4][2];
            #pragma unroll
            for (int mf = 0; mf < 4; mf++) {
                uint4 h = ZH[(sg * 8 + wm * 4 + mf) * 32 + lane];
                ah[mf][0] = h.x; ah[mf][1] = h.y; ah[mf][2] = h.z; ah[mf][3] = h.w;
                uint4 lo = ZL[(sg * 8 + wm * 4 + mf) * 32 + lane];
                al[mf][0] = lo.x; al[mf][1] = lo.y; al[mf][2] = lo.z; al[mf][3] = lo.w;
            }
            #pragma unroll
            for (int f = 0; f < 4; f++) {
                uint2 h = Bp[((s * 2 + 0) * 16 + wn * 4 + f) * 32 + lane];
                bh[f][0] = h.x; bh[f][1] = h.y;
                uint2 lo = Bp[((s * 2 + 1) * 16 + wn * 4 + f) * 32 + lane];
                bl[f][0] = lo.x; bl[f][1] = lo.y;
            }
            #pragma unroll
            for (int mf = 0; mf < 4; mf++)
                #pragma unroll
                for (int f = 0; f < 4; f++) {
                    MMA(acc[mf][f], ah[mf], bh[f]);
                    MMA(acc[mf][f], al[mf], bh[f]);
                    MMA(acc[mf][f], ah[mf], bl[f]);
                }
        }

        // ---- tile boundary: fold scores into running argmin, reset acc ----
        if (sti == 3) {
            const int t  = st >> 2;
            const int kb = t * 128 + wn * 32 + 2 * (lane & 3);
            #pragma unroll
            for (int mf = 0; mf < 4; mf++)
                #pragma unroll
                for (int f = 0; f < 4; f++)
                    #pragma unroll
                    for (int c = 0; c < 4; c++) {
                        int kn = kb + f * 8 + (c & 1);
                        float sc = fmaf(-2.0f, acc[mf][f][c], sm[CN_OFF + kn]);
                        int i = mf * 2 + (c >> 1);
                        if (sc < minv[i]) { minv[i] = sc; mini[i] = kn; }
                        acc[mf][f][c] = 0.0f;
                    }
        }
        __syncthreads();
    }

    // ---- cross-thread argmin combine (16 partials per row) ----
    float* rv   = sm + BB_OFF;                  // [128][16]
    int*   ri   = (int*)(sm + BB_OFF + 2048);   // [128][16]
    int*   fidx = (int*)(sm + BB_OFF + 4096);   // [128]
    #pragma unroll
    for (int i = 0; i < 8; i++) {
        int mfl = i >> 1, rh = i & 1;
        int m = wm * 64 + mfl * 16 + rh * 8 + (lane >> 2);
        int slot = wn * 4 + (lane & 3);
        rv[m * 16 + slot] = minv[i];
        ri[m * 16 + slot] = mini[i];
    }
    __syncthreads();
    if (tid < MT) {
        float bv = rv[tid * 16];
        int   bi = ri[tid * 16];
        #pragma unroll
        for (int t = 1; t < 16; t++) {
            float v = rv[tid * 16 + t];
            int  id = ri[tid * 16 + t];
            if (v < bv || (v == bv && id < bi)) { bv = v; bi = id; }
        }
        fidx[tid] = bi;
    }
    __syncthreads();

    // ---- gather + write output (codebook is L2-hot) ----
    const float4* cb4 = (const float4*)cb;
    float4* out4 = (float4*)out;
    for (int i = tid; i < MT * (DIM / 4); i += 256) {
        int m = i >> 5, c = i & 31;
        out4[(size_t)(m0 + m) * 32 + c] = cb4[(size_t)fidx[m] * 32 + c];
    }
}

// ---------------------------------------------------------------------------
extern "C" void kernel_launch(void* const* d_in, const int* in_sizes, int n_in,
                              void* d_out, int out_size) {
    const float* ze = (const float*)d_in[0];   // [65536, 128]
    const float* cb = (const float*)d_in[1];   // [2048, 128]
    float* out = (float*)d_out;
    (void)in_sizes; (void)n_in; (void)out_size;

    cudaFuncSetAttribute(vq_main,
                         cudaFuncAttributeMaxDynamicSharedMemorySize,
                         SMEM_BYTES);

    cnorm_kernel<<<KCB / 8, 256>>>(cb);
    bprep_kernel<<<NSTG, 256>>>(cb);
    vq_main<<<NWIN / MT, 256, SMEM_BYTES>>>(ze, cb, out);
}